// round 12
// baseline (speedup 1.0000x reference)
#include <cuda_runtime.h>
#include <cstdint>
#include <math.h>

#define B_   256
#define T_   256
#define D_   512
#define H_   512
#define O_   256
#define EPS_ 1e-5f

#define TJ_  32    // j-tile per GEMM CTA
#define TK_  16    // k-tile (double buffered)
#define GT_  256   // GEMM threads per CTA
#define NTILE_ (512 / TK_)
#define WSTR_ 34   // W smem row stride in ull (padded vs 32 to cut STS conflicts)

typedef unsigned long long ull;

// ---------------- static device scratch ----------------
__device__ float d_xT  [(size_t)T_ * D_ * B_];   // x transposed: [t][k][i]
__device__ float d_bufA[(size_t)T_ * H_ * B_];   // Z buffers [t][j][i]
__device__ float d_bufB[(size_t)T_ * H_ * B_];   // H buffers [t][j][i]

// ---------------- packed f32x2 helpers ----------------
__device__ __forceinline__ ull pk2(float x, float y) {
    ull r; asm("mov.b64 %0, {%1, %2};" : "=l"(r) : "f"(x), "f"(y)); return r;
}
__device__ __forceinline__ void upk2(float& x, float& y, ull v) {
    asm("mov.b64 {%0, %1}, %2;" : "=f"(x), "=f"(y) : "l"(v));
}
__device__ __forceinline__ void fma2(ull& d, ull a, ull b) {
    asm("fma.rn.f32x2 %0, %1, %2, %0;" : "+l"(d) : "l"(a), "l"(b));
}
__device__ __forceinline__ void cp_async16(unsigned saddr, const void* gaddr) {
    asm volatile("cp.async.cg.shared.global [%0], [%1], 16;"
                 :: "r"(saddr), "l"(gaddr));
}
#define CP_COMMIT() asm volatile("cp.async.commit_group;")
#define CP_WAIT0()  asm volatile("cp.async.wait_group 0;")

// ---------------- transpose x: [B][T][D] -> [T][D][B] ----------------
__global__ void transpose_kernel(const float* __restrict__ x) {
    __shared__ float sm[32][33];
    int t  = blockIdx.x;
    int k0 = blockIdx.y * 32;
    int i0 = blockIdx.z * 32;
    int tx = threadIdx.x, ty = threadIdx.y;
    sm[ty][tx] = x[((size_t)(i0 + ty) * T_ + t) * D_ + (k0 + tx)];
    __syncthreads();
    d_xT[((size_t)t * D_ + (k0 + ty)) * B_ + (i0 + tx)] = sm[tx][ty];
}

// ---------------- GEMM + fused BN1 (cp.async pipelined, 3 CTAs/SM) ----------
// OUT[t][j][i] = BN1_over_i( sum_k W[j][k] * IN[t][k][i] )   (bias cancels in BN)
// grid (T_, H_/TJ_) = (256,16), block 256.
// Warp w (0..7) owns i-octant [w*32, w*32+32); all warps cover the same 32 j's.
// Lane: jg = l&3 (j group), ig = l>>2 (i sub-group of 4).
// Thread j's: (m>>2)*16 + jg*4 + (m&3), m=0..7;  thread i's: w*32 + ig*4 + {0..3}.
#define X_BYTES     (TK_ * B_ * 4)                 // 16KB
#define W_BYTES     (TK_ * WSTR_ * 8)              // 4352B
#define STAGE_BYTES (X_BYTES + W_BYTES)            // 20736B
#define GEMM_SMEM   (2 * STAGE_BYTES)              // ~41.5KB -> 3 CTAs/SM

__global__ void __launch_bounds__(GT_, 3) gemm_bn_kernel(
    const float* __restrict__ IN, const float* __restrict__ W,
    const float* __restrict__ bias, const float* __restrict__ gam,
    const float* __restrict__ bet, float* __restrict__ OUT) {

    extern __shared__ __align__(16) char smraw[];
    const int t   = blockIdx.x;
    const int j0  = blockIdx.y * TJ_;
    const int tid = threadIdx.x;
    const int w   = tid >> 5;         // warp -> i octant
    const int jg  = tid & 3;          // j group
    const int ig  = (tid & 31) >> 2;  // i sub-group

    float* Xs[2] = { (float*)smraw, (float*)(smraw + STAGE_BYTES) };
    ull*   Ws[2] = { (ull*)(smraw + X_BYTES),
                     (ull*)(smraw + STAGE_BYTES + X_BYTES) };
    unsigned xsa[2] = { (unsigned)__cvta_generic_to_shared(Xs[0]),
                        (unsigned)__cvta_generic_to_shared(Xs[1]) };

    const float* inT = IN + (size_t)t * 512 * 256;
    // W staging roles (threads 0..127 only): jl = row (0..31), kf = float4 within tile
    const int jl = tid >> 2;
    const int kf = tid & 3;
    const float* wrow = W + (size_t)(j0 + jl) * 512 + 4 * kf;

    ull acc[8][2];
    #pragma unroll
    for (int m = 0; m < 8; m++) { acc[m][0] = 0ull; acc[m][1] = 0ull; }

    // --- preamble: stage tile 0 ---
    #pragma unroll
    for (int m = 0; m < 4; m++) {
        int idx = m * GT_ + tid;
        int r = idx >> 6, c = idx & 63;
        cp_async16(xsa[0] + (unsigned)(r * 1024 + c * 16),
                   inT + (size_t)r * 256 + c * 4);
    }
    CP_COMMIT();
    float4 wr = (tid < 128) ? *(const float4*)(wrow) : make_float4(0, 0, 0, 0);
    CP_WAIT0();
    if (tid < 128) {
        ull* wd = Ws[0] + (4 * kf) * WSTR_ + jl;
        wd[0 * WSTR_] = pk2(wr.x, wr.x); wd[1 * WSTR_] = pk2(wr.y, wr.y);
        wd[2 * WSTR_] = pk2(wr.z, wr.z); wd[3 * WSTR_] = pk2(wr.w, wr.w);
    }
    __syncthreads();

    // --- pipelined tile loop ---
    for (int it = 0; it < NTILE_; it++) {
        const int cur = it & 1, nxt = cur ^ 1;
        const int ktn = (it + 1) * TK_;
        if (it + 1 < NTILE_) {
            #pragma unroll
            for (int m = 0; m < 4; m++) {
                int idx = m * GT_ + tid;
                int r = idx >> 6, c = idx & 63;
                cp_async16(xsa[nxt] + (unsigned)(r * 1024 + c * 16),
                           inT + (size_t)(ktn + r) * 256 + c * 4);
            }
            CP_COMMIT();
            if (tid < 128) wr = *(const float4*)(wrow + ktn);
        }

        // compute on cur
        const float* xb = Xs[cur] + w * 32 + ig * 4;
        const ull*   wb = Ws[cur] + jg * 4;
        #pragma unroll 4
        for (int k = 0; k < TK_; k++) {
            ulonglong2 xa = *(const ulonglong2*)(xb + k * 256);
            const ull* wk = wb + k * WSTR_;
            ulonglong2 wA = *(const ulonglong2*)(wk);
            ulonglong2 wB = *(const ulonglong2*)(wk + 2);
            ulonglong2 wC = *(const ulonglong2*)(wk + 16);
            ulonglong2 wD = *(const ulonglong2*)(wk + 18);
            fma2(acc[0][0], xa.x, wA.x); fma2(acc[0][1], xa.y, wA.x);
            fma2(acc[1][0], xa.x, wA.y); fma2(acc[1][1], xa.y, wA.y);
            fma2(acc[2][0], xa.x, wB.x); fma2(acc[2][1], xa.y, wB.x);
            fma2(acc[3][0], xa.x, wB.y); fma2(acc[3][1], xa.y, wB.y);
            fma2(acc[4][0], xa.x, wC.x); fma2(acc[4][1], xa.y, wC.x);
            fma2(acc[5][0], xa.x, wC.y); fma2(acc[5][1], xa.y, wC.y);
            fma2(acc[6][0], xa.x, wD.x); fma2(acc[6][1], xa.y, wD.x);
            fma2(acc[7][0], xa.x, wD.y); fma2(acc[7][1], xa.y, wD.y);
        }

        if (it + 1 < NTILE_ && tid < 128) {
            ull* wd = Ws[nxt] + (4 * kf) * WSTR_ + jl;
            wd[0 * WSTR_] = pk2(wr.x, wr.x); wd[1 * WSTR_] = pk2(wr.y, wr.y);
            wd[2 * WSTR_] = pk2(wr.z, wr.z); wd[3 * WSTR_] = pk2(wr.w, wr.w);
        }
        CP_WAIT0();
        __syncthreads();
    }

    // ---- epilogue: BN1 per j (intra-warp over ig, cross-warp over 8 octants) --
    __syncthreads();                    // all tiles consumed; reuse smem
    float* sstat = (float*)smraw;       // [8 w][4 jg][8 m][2] = 2KB

    float ls1[8], ls2[8];
    #pragma unroll
    for (int m = 0; m < 8; m++) {
        float v0, v1, v2, v3;
        upk2(v0, v1, acc[m][0]);
        upk2(v2, v3, acc[m][1]);
        ls1[m] = v0 + v1 + v2 + v3;
        ls2[m] = v0 * v0 + v1 * v1 + v2 * v2 + v3 * v3;
    }
    #pragma unroll
    for (int off = 4; off <= 16; off <<= 1) {
        #pragma unroll
        for (int m = 0; m < 8; m++) {
            ls1[m] += __shfl_xor_sync(0xffffffffu, ls1[m], off);
            ls2[m] += __shfl_xor_sync(0xffffffffu, ls2[m], off);
        }
    }
    if (ig == 0) {
        float* sp = sstat + ((w * 4 + jg) * 8) * 2;
        #pragma unroll
        for (int m = 0; m < 8; m++) { sp[2 * m] = ls1[m]; sp[2 * m + 1] = ls2[m]; }
    }
    __syncthreads();

    #pragma unroll
    for (int m = 0; m < 8; m++) {
        int j = j0 + ((m >> 2) << 4) + jg * 4 + (m & 3);
        float s1 = 0.f, s2 = 0.f;
        #pragma unroll
        for (int w2 = 0; w2 < 8; w2++) {
            const float* sp = sstat + ((w2 * 4 + jg) * 8 + m) * 2;
            s1 += sp[0]; s2 += sp[1];
        }
        float mn  = s1 * (1.f / B_);
        float var = s2 * (1.f / B_) - mn * mn;
        float sc  = rsqrtf(var + EPS_) * gam[j];
        float sh  = bet[j] - mn * sc;
        float a0, a1, a2, a3;
        upk2(a0, a1, acc[m][0]); upk2(a2, a3, acc[m][1]);
        float* op = OUT + ((size_t)t * 512 + j) * 256 + w * 32 + ig * 4;
        *(float4*)(op) = make_float4(a0 * sc + sh, a1 * sc + sh,
                                     a2 * sc + sh, a3 * sc + sh);
    }
    (void)bias;
}

// ---------------- sequential state scan: warp-per-column, no block syncs ----
__global__ void __launch_bounds__(128) scan_kernel(
    const float* __restrict__ Z, const float* __restrict__ u,
    const float* __restrict__ g2, const float* __restrict__ be2,
    float* __restrict__ OUT) {

    const int tid  = threadIdx.x;
    const int w    = tid >> 5;
    const int lane = tid & 31;
    const int j    = blockIdx.x * 4 + w;
    const size_t base = (size_t)j * 256 + 8 * lane;
    const size_t tstr = (size_t)512 * 256;

    const float uv = u[j], gv = g2[j], bv = be2[j];
    float h[8];
    #pragma unroll
    for (int q = 0; q < 8; q++) h[q] = 0.f;

    float4 zc0 = *(const float4*)(Z + base);
    float4 zc1 = *(const float4*)(Z + base + 4);
    float4 zn0 = *(const float4*)(Z + tstr + base);
    float4 zn1 = *(const float4*)(Z + tstr + base + 4);

    for (int t = 0; t < T_; t++) {
        float y[8];
        y[0] = fmaxf(fmaf(h[0], uv, zc0.x), 0.f);
        y[1] = fmaxf(fmaf(h[1], uv, zc0.y), 0.f);
        y[2] = fmaxf(fmaf(h[2], uv, zc0.z), 0.f);
        y[3] = fmaxf(fmaf(h[3], uv, zc0.w), 0.f);
        y[4] = fmaxf(fmaf(h[4], uv, zc1.x), 0.f);
        y[5] = fmaxf(fmaf(h[5], uv, zc1.y), 0.f);
        y[6] = fmaxf(fmaf(h[6], uv, zc1.z), 0.f);
        y[7] = fmaxf(fmaf(h[7], uv, zc1.w), 0.f);

        zc0 = zn0; zc1 = zn1;
        if (t + 2 < T_) {
            zn0 = *(const float4*)(Z + (size_t)(t + 2) * tstr + base);
            zn1 = *(const float4*)(Z + (size_t)(t + 2) * tstr + base + 4);
        }

        float s1 = 0.f, s2 = 0.f;
        #pragma unroll
        for (int q = 0; q < 8; q++) { s1 += y[q]; s2 += y[q] * y[q]; }
        #pragma unroll
        for (int off = 16; off > 0; off >>= 1) {
            s1 += __shfl_xor_sync(0xffffffffu, s1, off);
            s2 += __shfl_xor_sync(0xffffffffu, s2, off);
        }
        float m   = s1 * (1.f / B_);
        float var = s2 * (1.f / B_) - m * m;
        float sc  = rsqrtf(var + EPS_) * gv;
        float sh  = bv - m * sc;
        #pragma unroll
        for (int q = 0; q < 8; q++) h[q] = y[q] * sc + sh;

        float* op = OUT + (size_t)t * tstr + base;
        *(float4*)(op)     = make_float4(h[0], h[1], h[2], h[3]);
        *(float4*)(op + 4) = make_float4(h[4], h[5], h[6], h[7]);
    }
}

// ---------------- head: logits + log_softmax ----------------
__global__ void __launch_bounds__(256) head_kernel(
    const float* __restrict__ HM,
    const float* __restrict__ Wfc, const float* __restrict__ bfc,
    float* __restrict__ out) {

    __shared__ float hrow[H_];
    __shared__ float shd[8];

    const int r   = blockIdx.x;
    const int tid = threadIdx.x;

    hrow[tid]       = HM[(size_t)tid * 256 + r];
    hrow[tid + 256] = HM[(size_t)(tid + 256) * 256 + r];
    __syncthreads();

    float acc = bfc[tid];
    const float4* wrow = (const float4*)(Wfc + (size_t)tid * H_);
    #pragma unroll 4
    for (int j4 = 0; j4 < H_ / 4; j4++) {
        float4 w = wrow[j4];
        acc = fmaf(hrow[4 * j4 + 0], w.x, acc);
        acc = fmaf(hrow[4 * j4 + 1], w.y, acc);
        acc = fmaf(hrow[4 * j4 + 2], w.z, acc);
        acc = fmaf(hrow[4 * j4 + 3], w.w, acc);
    }

    float v = acc;
    #pragma unroll
    for (int off = 16; off > 0; off >>= 1)
        v = fmaxf(v, __shfl_xor_sync(0xffffffffu, v, off));
    if ((tid & 31) == 0) shd[tid >> 5] = v;
    __syncthreads();
    float mx = shd[0];
    #pragma unroll
    for (int w = 1; w < 8; w++) mx = fmaxf(mx, shd[w]);
    __syncthreads();

    float e = expf(acc - mx);
    float sv = e;
    #pragma unroll
    for (int off = 16; off > 0; off >>= 1)
        sv += __shfl_xor_sync(0xffffffffu, sv, off);
    if ((tid & 31) == 0) shd[tid >> 5] = sv;
    __syncthreads();
    float se = 0.f;
    #pragma unroll
    for (int w = 0; w < 8; w++) se += shd[w];

    out[(size_t)r * O_ + tid] = acc - mx - logf(se);
}

// ---------------- harness entry ----------------
extern "C" void kernel_launch(void* const* d_in, const int* in_sizes, int n_in,
                              void* d_out, int out_size) {
    (void)in_sizes; (void)n_in; (void)out_size;
    const float* x    = (const float*)d_in[0];
    const float* W0   = (const float*)d_in[1];
    const float* b0   = (const float*)d_in[2];
    const float* u0   = (const float*)d_in[3];
    const float* g10  = (const float*)d_in[4];
    const float* be10 = (const float*)d_in[5];
    const float* g20  = (const float*)d_in[6];
    const float* be20 = (const float*)d_in[7];
    const float* Wm   = (const float*)d_in[8];
    const float* bm   = (const float*)d_in[9];
    const float* um   = (const float*)d_in[10];
    const float* g1m  = (const float*)d_in[11];
    const float* be1m = (const float*)d_in[12];
    const float* g2m  = (const float*)d_in[13];
    const float* be2m = (const float*)d_in[14];
    const float* Wfc  = (const float*)d_in[15];
    const float* bfc  = (const float*)d_in[16];
    float* out = (float*)d_out;

    float* bufA;  cudaGetSymbolAddress((void**)&bufA, d_bufA);
    float* bufB;  cudaGetSymbolAddress((void**)&bufB, d_bufB);
    float* xT;    cudaGetSymbolAddress((void**)&xT,   d_xT);

    transpose_kernel<<<dim3(T_, D_ / 32, B_ / 32), dim3(32, 32)>>>(x);
    gemm_bn_kernel<<<dim3(T_, H_ / TJ_), GT_, GEMM_SMEM>>>(xT, W0, b0, g10, be10, bufA);
    scan_kernel<<<128, 128>>>(bufA, u0, g20, be20, bufB);
    gemm_bn_kernel<<<dim3(T_, H_ / TJ_), GT_, GEMM_SMEM>>>(bufB, Wm, bm, g1m, be1m, bufA);
    scan_kernel<<<128, 128>>>(bufA, um, g2m, be2m, bufB);
    gemm_bn_kernel<<<dim3(T_, H_ / TJ_), GT_, GEMM_SMEM>>>(bufB, Wm, bm, g1m, be1m, bufA);
    scan_kernel<<<128, 128>>>(bufA, um, g2m, be2m, bufB);
    head_kernel<<<O_, 256>>>(bufB + (size_t)(T_ - 1) * H_ * B_, Wfc, bfc, out);
}

// round 13
// speedup vs baseline: 1.5785x; 1.5785x over previous
#include <cuda_runtime.h>
#include <cstdint>
#include <math.h>

#define B_   256
#define T_   256
#define D_   512
#define H_   512
#define O_   256
#define EPS_ 1e-5f

#define TJ_  64    // j-tile per GEMM CTA
#define TK_  32    // k-tile (double buffered)
#define GT_  256   // GEMM threads per CTA
#define NTILE_ (512 / TK_)

typedef unsigned long long ull;

// ---------------- static device scratch ----------------
__device__ float d_xT  [(size_t)T_ * D_ * B_];   // x transposed: [t][k][i]
__device__ float d_bufA[(size_t)T_ * H_ * B_];   // Z buffers [t][j][i]
__device__ float d_bufB[(size_t)T_ * H_ * B_];   // H buffers [t][j][i]

// ---------------- packed f32x2 helpers ----------------
__device__ __forceinline__ ull pk2(float x, float y) {
    ull r; asm("mov.b64 %0, {%1, %2};" : "=l"(r) : "f"(x), "f"(y)); return r;
}
__device__ __forceinline__ void upk2(float& x, float& y, ull v) {
    asm("mov.b64 {%0, %1}, %2;" : "=f"(x), "=f"(y) : "l"(v));
}
__device__ __forceinline__ void fma2(ull& d, ull a, ull b) {
    asm("fma.rn.f32x2 %0, %1, %2, %0;" : "+l"(d) : "l"(a), "l"(b));
}
__device__ __forceinline__ void cp_async16(unsigned saddr, const void* gaddr) {
    asm volatile("cp.async.cg.shared.global [%0], [%1], 16;"
                 :: "r"(saddr), "l"(gaddr));
}
#define CP_COMMIT() asm volatile("cp.async.commit_group;")
#define CP_WAIT0()  asm volatile("cp.async.wait_group 0;")
#define CP_WAIT6()  asm volatile("cp.async.wait_group 6;")

// ---------------- transpose x: [B][T][D] -> [T][D][B] ----------------
__global__ void transpose_kernel(const float* __restrict__ x) {
    __shared__ float sm[32][33];
    int t  = blockIdx.x;
    int k0 = blockIdx.y * 32;
    int i0 = blockIdx.z * 32;
    int tx = threadIdx.x, ty = threadIdx.y;
    sm[ty][tx] = x[((size_t)(i0 + ty) * T_ + t) * D_ + (k0 + tx)];
    __syncthreads();
    d_xT[((size_t)t * D_ + (k0 + ty)) * B_ + (i0 + tx)] = sm[tx][ty];
}

// ---------------- GEMM + fused BN1 (R10 proven: cp.async double-buffered) ---
// OUT[t][j][i] = BN1_over_i( sum_k W[j][k] * IN[t][k][i] + bias[j] )
// grid (T_, H_/TJ_), block 256. Warp jq owns 8 j's; lane ip owns i-pairs
// {ip+32q, q<4} -> warp covers full batch -> BN1 = warp shuffle reduction.
#define STAGE_BYTES (TK_ * B_ * 4 + TK_ * TJ_ * 8)   // 32KB X + 16KB W = 48KB
#define GEMM_SMEM   (2 * STAGE_BYTES)                 // 96KB

__global__ void __launch_bounds__(GT_, 2) gemm_bn_kernel(
    const float* __restrict__ IN, const float* __restrict__ W,
    const float* __restrict__ bias, const float* __restrict__ gam,
    const float* __restrict__ bet, float* __restrict__ OUT) {

    extern __shared__ __align__(16) char smraw[];
    const int t   = blockIdx.x;
    const int j0  = blockIdx.y * TJ_;
    const int tid = threadIdx.x;
    const int jq  = tid >> 5;     // warp -> j octet
    const int ip  = tid & 31;     // lane -> i pairs {ip+32q}
    const int jl  = tid >> 2;     // W-stage row (0..63)
    const int kq  = tid & 3;      // W-stage k octet

    float* Xs[2] = { (float*)smraw, (float*)(smraw + STAGE_BYTES) };
    ull*   Ws[2] = { (ull*)(smraw + TK_ * B_ * 4),
                     (ull*)(smraw + STAGE_BYTES + TK_ * B_ * 4) };
    unsigned xsa[2] = { (unsigned)__cvta_generic_to_shared(Xs[0]),
                        (unsigned)__cvta_generic_to_shared(Xs[1]) };

    const float* inT = IN + (size_t)t * 512 * 256;
    const float* wrow = W + (size_t)(j0 + jl) * 512 + 8 * kq;

    ull acc[8][4];
    #pragma unroll
    for (int jj = 0; jj < 8; jj++)
        #pragma unroll
        for (int q = 0; q < 4; q++) acc[jj][q] = 0ull;

    // --- preamble: stage tile 0 ---
    #pragma unroll
    for (int m = 0; m < 8; m++) {
        int idx = m * GT_ + tid;
        int r = idx >> 6, c = idx & 63;
        cp_async16(xsa[0] + (unsigned)(r * 1024 + c * 16),
                   inT + (size_t)r * 256 + c * 4);
    }
    CP_COMMIT();
    float4 wr0 = *(const float4*)(wrow);
    float4 wr1 = *(const float4*)(wrow + 4);
    CP_WAIT0();
    {
        ull* wd = Ws[0] + (8 * kq) * TJ_ + jl;
        wd[0 * TJ_] = pk2(wr0.x, wr0.x); wd[1 * TJ_] = pk2(wr0.y, wr0.y);
        wd[2 * TJ_] = pk2(wr0.z, wr0.z); wd[3 * TJ_] = pk2(wr0.w, wr0.w);
        wd[4 * TJ_] = pk2(wr1.x, wr1.x); wd[5 * TJ_] = pk2(wr1.y, wr1.y);
        wd[6 * TJ_] = pk2(wr1.z, wr1.z); wd[7 * TJ_] = pk2(wr1.w, wr1.w);
    }
    __syncthreads();

    // --- pipelined tile loop ---
    for (int it = 0; it < NTILE_; it++) {
        const int cur = it & 1, nxt = cur ^ 1;
        const int ktn = (it + 1) * TK_;
        if (it + 1 < NTILE_) {
            #pragma unroll
            for (int m = 0; m < 8; m++) {
                int idx = m * GT_ + tid;
                int r = idx >> 6, c = idx & 63;
                cp_async16(xsa[nxt] + (unsigned)(r * 1024 + c * 16),
                           inT + (size_t)(ktn + r) * 256 + c * 4);
            }
            CP_COMMIT();
            wr0 = *(const float4*)(wrow + ktn);
            wr1 = *(const float4*)(wrow + ktn + 4);
        }

        // compute on cur
        const float* xb = Xs[cur];
        const ull*   wb = Ws[cur] + jq * 8;
        #pragma unroll 4
        for (int k = 0; k < TK_; k++) {
            const float* xr = xb + k * 256;
            ull xv0 = *(const ull*)(xr + 2 * ip);
            ull xv1 = *(const ull*)(xr + 2 * ip + 64);
            ull xv2 = *(const ull*)(xr + 2 * ip + 128);
            ull xv3 = *(const ull*)(xr + 2 * ip + 192);
            const ulonglong2* wr = (const ulonglong2*)(wb + k * TJ_);
            ulonglong2 wa = wr[0], wbb = wr[1], wc = wr[2], wd = wr[3];
            fma2(acc[0][0], xv0, wa.x);  fma2(acc[0][1], xv1, wa.x);
            fma2(acc[0][2], xv2, wa.x);  fma2(acc[0][3], xv3, wa.x);
            fma2(acc[1][0], xv0, wa.y);  fma2(acc[1][1], xv1, wa.y);
            fma2(acc[1][2], xv2, wa.y);  fma2(acc[1][3], xv3, wa.y);
            fma2(acc[2][0], xv0, wbb.x); fma2(acc[2][1], xv1, wbb.x);
            fma2(acc[2][2], xv2, wbb.x); fma2(acc[2][3], xv3, wbb.x);
            fma2(acc[3][0], xv0, wbb.y); fma2(acc[3][1], xv1, wbb.y);
            fma2(acc[3][2], xv2, wbb.y); fma2(acc[3][3], xv3, wbb.y);
            fma2(acc[4][0], xv0, wc.x);  fma2(acc[4][1], xv1, wc.x);
            fma2(acc[4][2], xv2, wc.x);  fma2(acc[4][3], xv3, wc.x);
            fma2(acc[5][0], xv0, wc.y);  fma2(acc[5][1], xv1, wc.y);
            fma2(acc[5][2], xv2, wc.y);  fma2(acc[5][3], xv3, wc.y);
            fma2(acc[6][0], xv0, wd.x);  fma2(acc[6][1], xv1, wd.x);
            fma2(acc[6][2], xv2, wd.x);  fma2(acc[6][3], xv3, wd.x);
            fma2(acc[7][0], xv0, wd.y);  fma2(acc[7][1], xv1, wd.y);
            fma2(acc[7][2], xv2, wd.y);  fma2(acc[7][3], xv3, wd.y);
        }

        if (it + 1 < NTILE_) {
            ull* wd2 = Ws[nxt] + (8 * kq) * TJ_ + jl;
            wd2[0 * TJ_] = pk2(wr0.x, wr0.x); wd2[1 * TJ_] = pk2(wr0.y, wr0.y);
            wd2[2 * TJ_] = pk2(wr0.z, wr0.z); wd2[3 * TJ_] = pk2(wr0.w, wr0.w);
            wd2[4 * TJ_] = pk2(wr1.x, wr1.x); wd2[5 * TJ_] = pk2(wr1.y, wr1.y);
            wd2[6 * TJ_] = pk2(wr1.z, wr1.z); wd2[7 * TJ_] = pk2(wr1.w, wr1.w);
        }
        CP_WAIT0();
        __syncthreads();
    }

    // ---- epilogue: bias + BN1 per j (warp-local stats), store ----
    #pragma unroll
    for (int jj = 0; jj < 8; jj++) {
        int j = j0 + jq * 8 + jj;
        float bb = bias[j];
        float z[8];
        #pragma unroll
        for (int q = 0; q < 4; q++) {
            float a, b2;
            upk2(a, b2, acc[jj][q]);
            z[2 * q] = a + bb; z[2 * q + 1] = b2 + bb;
        }
        float s1 = 0.f, s2 = 0.f;
        #pragma unroll
        for (int q = 0; q < 8; q++) { s1 += z[q]; s2 += z[q] * z[q]; }
        #pragma unroll
        for (int off = 16; off > 0; off >>= 1) {
            s1 += __shfl_xor_sync(0xffffffffu, s1, off);
            s2 += __shfl_xor_sync(0xffffffffu, s2, off);
        }
        float m   = s1 * (1.f / B_);
        float var = s2 * (1.f / B_) - m * m;
        float sc  = rsqrtf(var + EPS_) * gam[j];
        float sh  = bet[j] - m * sc;
        float* op = OUT + ((size_t)t * 512 + j) * 256;
        #pragma unroll
        for (int q = 0; q < 4; q++) {
            float ox = z[2 * q] * sc + sh;
            float oy = z[2 * q + 1] * sc + sh;
            *(ull*)(op + 2 * (ip + 32 * q)) = pk2(ox, oy);
        }
    }
}

// ---------------- sequential state scan: cp.async ring, warp-per-column -----
// h(t) = BN2_over_i( relu(Z[t] + h(t-1) * u) );  OUT[t] = h(t)
// grid 128, block 128: warp w owns column j = blockIdx*4 + w,
// lane owns batch elems 8*lane..8*lane+7 (32B) — streams its OWN 32B per t
// through a private 8-stage smem ring (no cross-lane sharing, no syncs).
__global__ void __launch_bounds__(128) scan_kernel(
    const float* __restrict__ Z, const float* __restrict__ u,
    const float* __restrict__ g2, const float* __restrict__ be2,
    float* __restrict__ OUT) {

    __shared__ __align__(16) float ring[4][8][256];   // [warp][stage][i] 32KB

    const int tid  = threadIdx.x;
    const int w    = tid >> 5;
    const int lane = tid & 31;
    const int j    = blockIdx.x * 4 + w;
    const size_t base = (size_t)j * 256 + 8 * lane;
    const size_t tstr = (size_t)512 * 256;

    const float* zsrc = Z + base;
    float* hdst = OUT + base;
    float* myring = &ring[w][0][lane * 8];
    const unsigned rbase = (unsigned)__cvta_generic_to_shared(myring);

    const float uv = u[j], gv = g2[j], bv = be2[j];
    float h[8];
    #pragma unroll
    for (int q = 0; q < 8; q++) h[q] = 0.f;

    // preload stages 0..6 (one commit group per stage)
    #pragma unroll
    for (int s = 0; s < 7; s++) {
        cp_async16(rbase + (unsigned)(s * 1024),      zsrc + (size_t)s * tstr);
        cp_async16(rbase + (unsigned)(s * 1024) + 16, zsrc + (size_t)s * tstr + 4);
        CP_COMMIT();
    }

    for (int t = 0; t < T_; t++) {
        CP_WAIT6();    // stage t resident (own data; no cross-lane use)
        const float* zr = myring + (t & 7) * 256;
        float4 z0 = *(const float4*)(zr);
        float4 z1 = *(const float4*)(zr + 4);

        // prefetch stage t+7
        int tp = t + 7;
        if (tp < T_) {
            cp_async16(rbase + (unsigned)((tp & 7) * 1024),
                       zsrc + (size_t)tp * tstr);
            cp_async16(rbase + (unsigned)((tp & 7) * 1024) + 16,
                       zsrc + (size_t)tp * tstr + 4);
        }
        CP_COMMIT();

        float y[8];
        y[0] = fmaxf(fmaf(h[0], uv, z0.x), 0.f);
        y[1] = fmaxf(fmaf(h[1], uv, z0.y), 0.f);
        y[2] = fmaxf(fmaf(h[2], uv, z0.z), 0.f);
        y[3] = fmaxf(fmaf(h[3], uv, z0.w), 0.f);
        y[4] = fmaxf(fmaf(h[4], uv, z1.x), 0.f);
        y[5] = fmaxf(fmaf(h[5], uv, z1.y), 0.f);
        y[6] = fmaxf(fmaf(h[6], uv, z1.z), 0.f);
        y[7] = fmaxf(fmaf(h[7], uv, z1.w), 0.f);

        float s1 = 0.f, s2 = 0.f;
        #pragma unroll
        for (int q = 0; q < 8; q++) { s1 += y[q]; s2 += y[q] * y[q]; }
        #pragma unroll
        for (int off = 16; off > 0; off >>= 1) {
            s1 += __shfl_xor_sync(0xffffffffu, s1, off);
            s2 += __shfl_xor_sync(0xffffffffu, s2, off);
        }
        float m   = s1 * (1.f / B_);
        float var = s2 * (1.f / B_) - m * m;
        float sc  = rsqrtf(var + EPS_) * gv;
        float sh  = bv - m * sc;
        #pragma unroll
        for (int q = 0; q < 8; q++) h[q] = y[q] * sc + sh;

        float* op = hdst + (size_t)t * tstr;
        *(float4*)(op)     = make_float4(h[0], h[1], h[2], h[3]);
        *(float4*)(op + 4) = make_float4(h[4], h[5], h[6], h[7]);
    }
}

// ---------------- head: logits + log_softmax ----------------
__global__ void __launch_bounds__(256) head_kernel(
    const float* __restrict__ HM,
    const float* __restrict__ Wfc, const float* __restrict__ bfc,
    float* __restrict__ out) {

    __shared__ float hrow[H_];
    __shared__ float shd[8];

    const int r   = blockIdx.x;
    const int tid = threadIdx.x;

    hrow[tid]       = HM[(size_t)tid * 256 + r];
    hrow[tid + 256] = HM[(size_t)(tid + 256) * 256 + r];
    __syncthreads();

    float acc = bfc[tid];
    const float4* wrow = (const float4*)(Wfc + (size_t)tid * H_);
    #pragma unroll 4
    for (int j4 = 0; j4 < H_ / 4; j4++) {
        float4 w = wrow[j4];
        acc = fmaf(hrow[4 * j4 + 0], w.x, acc);
        acc = fmaf(hrow[4 * j4 + 1], w.y, acc);
        acc = fmaf(hrow[4 * j4 + 2], w.z, acc);
        acc = fmaf(hrow[4 * j4 + 3], w.w, acc);
    }

    float v = acc;
    #pragma unroll
    for (int off = 16; off > 0; off >>= 1)
        v = fmaxf(v, __shfl_xor_sync(0xffffffffu, v, off));
    if ((tid & 31) == 0) shd[tid >> 5] = v;
    __syncthreads();
    float mx = shd[0];
    #pragma unroll
    for (int w = 1; w < 8; w++) mx = fmaxf(mx, shd[w]);
    __syncthreads();

    float e = expf(acc - mx);
    float sv = e;
    #pragma unroll
    for (int off = 16; off > 0; off >>= 1)
        sv += __shfl_xor_sync(0xffffffffu, sv, off);
    if ((tid & 31) == 0) shd[tid >> 5] = sv;
    __syncthreads();
    float se = 0.f;
    #pragma unroll
    for (int w = 0; w < 8; w++) se += shd[w];

    out[(size_t)r * O_ + tid] = acc - mx - logf(se);
}

// ---------------- harness entry ----------------
extern "C" void kernel_launch(void* const* d_in, const int* in_sizes, int n_in,
                              void* d_out, int out_size) {
    (void)in_sizes; (void)n_in; (void)out_size;
    const float* x    = (const float*)d_in[0];
    const float* W0   = (const float*)d_in[1];
    const float* b0   = (const float*)d_in[2];
    const float* u0   = (const float*)d_in[3];
    const float* g10  = (const float*)d_in[4];
    const float* be10 = (const float*)d_in[5];
    const float* g20  = (const float*)d_in[6];
    const float* be20 = (const float*)d_in[7];
    const float* Wm   = (const float*)d_in[8];
    const float* bm   = (const float*)d_in[9];
    const float* um   = (const float*)d_in[10];
    const float* g1m  = (const float*)d_in[11];
    const float* be1m = (const float*)d_in[12];
    const float* g2m  = (const float*)d_in[13];
    const float* be2m = (const float*)d_in[14];
    const float* Wfc  = (const float*)d_in[15];
    const float* bfc  = (const float*)d_in[16];
    float* out = (float*)d_out;

    static int attr_set = 0;
    if (!attr_set) {
        cudaFuncSetAttribute(gemm_bn_kernel,
                             cudaFuncAttributeMaxDynamicSharedMemorySize, GEMM_SMEM);
        attr_set = 1;
    }

    float* bufA;  cudaGetSymbolAddress((void**)&bufA, d_bufA);
    float* bufB;  cudaGetSymbolAddress((void**)&bufB, d_bufB);
    float* xT;    cudaGetSymbolAddress((void**)&xT,   d_xT);

    transpose_kernel<<<dim3(T_, D_ / 32, B_ / 32), dim3(32, 32)>>>(x);
    gemm_bn_kernel<<<dim3(T_, H_ / TJ_), GT_, GEMM_SMEM>>>(xT, W0, b0, g10, be10, bufA);
    scan_kernel<<<128, 128>>>(bufA, u0, g20, be20, bufB);
    gemm_bn_kernel<<<dim3(T_, H_ / TJ_), GT_, GEMM_SMEM>>>(bufB, Wm, bm, g1m, be1m, bufA);
    scan_kernel<<<128, 128>>>(bufA, um, g2m, be2m, bufB);
    gemm_bn_kernel<<<dim3(T_, H_ / TJ_), GT_, GEMM_SMEM>>>(bufB, Wm, bm, g1m, be1m, bufA);
    scan_kernel<<<128, 128>>>(bufA, um, g2m, be2m, bufB);
    head_kernel<<<O_, 256>>>(bufB + (size_t)(T_ - 1) * H_ * B_, Wfc, bfc, out);
}

// round 14
// speedup vs baseline: 1.7817x; 1.1287x over previous
#include <cuda_runtime.h>
#include <cstdint>
#include <math.h>

#define B_   256
#define T_   256
#define D_   512
#define H_   512
#define O_   256
#define EPS_ 1e-5f

#define TJ_  64    // j-tile per GEMM CTA
#define TK_  32    // k-tile (double buffered)
#define GT_  256   // GEMM threads per CTA
#define NTILE_ (512 / TK_)
#define WRS_ 36    // Wraw row stride in floats (16B-aligned, bank-friendly)

typedef unsigned long long ull;

// ---------------- static device scratch ----------------
__device__ float d_xT  [(size_t)T_ * D_ * B_];   // x transposed: [t][k][i]
__device__ float d_bufA[(size_t)T_ * H_ * B_];   // Z buffers [t][j][i]
__device__ float d_bufB[(size_t)T_ * H_ * B_];   // H buffers [t][j][i]

// ---------------- packed f32x2 helpers ----------------
__device__ __forceinline__ ull pk2(float x, float y) {
    ull r; asm("mov.b64 %0, {%1, %2};" : "=l"(r) : "f"(x), "f"(y)); return r;
}
__device__ __forceinline__ void upk2(float& x, float& y, ull v) {
    asm("mov.b64 {%0, %1}, %2;" : "=f"(x), "=f"(y) : "l"(v));
}
__device__ __forceinline__ void fma2(ull& d, ull a, ull b) {
    asm("fma.rn.f32x2 %0, %1, %2, %0;" : "+l"(d) : "l"(a), "l"(b));
}
__device__ __forceinline__ void cp_async16(unsigned saddr, const void* gaddr) {
    asm volatile("cp.async.cg.shared.global [%0], [%1], 16;"
                 :: "r"(saddr), "l"(gaddr));
}
#define CP_COMMIT() asm volatile("cp.async.commit_group;")
#define CP_WAIT0()  asm volatile("cp.async.wait_group 0;")
#define CP_WAIT6()  asm volatile("cp.async.wait_group 6;")

// ---------------- transpose x: [B][T][D] -> [T][D][B] ----------------
__global__ void transpose_kernel(const float* __restrict__ x) {
    __shared__ float sm[32][33];
    int t  = blockIdx.x;
    int k0 = blockIdx.y * 32;
    int i0 = blockIdx.z * 32;
    int tx = threadIdx.x, ty = threadIdx.y;
    sm[ty][tx] = x[((size_t)(i0 + ty) * T_ + t) * D_ + (k0 + tx)];
    __syncthreads();
    d_xT[((size_t)t * D_ + (k0 + ty)) * B_ + (i0 + tx)] = sm[tx][ty];
}

// ---------------- GEMM + fused BN1 (all inputs via cp.async) ----------------
// OUT[t][j][i] = BN1_over_i( sum_k W[j][k] * IN[t][k][i] )   (bias cancels in BN)
// grid (T_, H_/TJ_), block 256. Warp jq owns 8 j's; lane ip owns i-pairs
// {ip+32q, q<4} -> warp covers full batch -> BN1 = warp shuffle reduction.
// W staged RAW via cp.async into padded smem; (w,w) packed in-register.
#define X_STAGE   (TK_ * B_ * 4)           // 32KB
#define WRAW_B    (TJ_ * WRS_ * 4)         // 9216B
#define GEMM_SMEM (2 * X_STAGE + 2 * WRAW_B)   // 83968B -> 2 CTAs/SM

__global__ void __launch_bounds__(GT_, 2) gemm_bn_kernel(
    const float* __restrict__ IN, const float* __restrict__ W,
    const float* __restrict__ bias, const float* __restrict__ gam,
    const float* __restrict__ bet, float* __restrict__ OUT) {

    extern __shared__ __align__(16) char smraw[];
    const int t   = blockIdx.x;
    const int j0  = blockIdx.y * TJ_;
    const int tid = threadIdx.x;
    const int jq  = tid >> 5;     // warp -> j octet
    const int ip  = tid & 31;     // lane -> i pairs {ip+32q}

    float* Xs[2] = { (float*)smraw, (float*)(smraw + X_STAGE) };
    float* Wr[2] = { (float*)(smraw + 2 * X_STAGE),
                     (float*)(smraw + 2 * X_STAGE + WRAW_B) };
    unsigned xsa[2] = { (unsigned)__cvta_generic_to_shared(Xs[0]),
                        (unsigned)__cvta_generic_to_shared(Xs[1]) };
    unsigned wsa[2] = { (unsigned)__cvta_generic_to_shared(Wr[0]),
                        (unsigned)__cvta_generic_to_shared(Wr[1]) };

    const float* inT = IN + (size_t)t * 512 * 256;
    const float* wbase = W + (size_t)j0 * 512;

    ull acc[8][4];
    #pragma unroll
    for (int jj = 0; jj < 8; jj++)
        #pragma unroll
        for (int q = 0; q < 4; q++) acc[jj][q] = 0ull;

    // --- preamble: stage tile 0 (X + Wraw) ---
    #pragma unroll
    for (int m = 0; m < 8; m++) {
        int idx = m * GT_ + tid;
        int r = idx >> 6, c = idx & 63;
        cp_async16(xsa[0] + (unsigned)(r * 1024 + c * 16),
                   inT + (size_t)r * 256 + c * 4);
    }
    #pragma unroll
    for (int m = 0; m < 2; m++) {
        int idx = m * GT_ + tid;              // 512 chunks of 16B
        int r = idx >> 3, c = idx & 7;
        cp_async16(wsa[0] + (unsigned)(r * (WRS_ * 4) + c * 16),
                   wbase + (size_t)r * 512 + c * 4);
    }
    CP_COMMIT();
    CP_WAIT0();
    __syncthreads();

    // --- pipelined tile loop ---
    for (int it = 0; it < NTILE_; it++) {
        const int cur = it & 1, nxt = cur ^ 1;
        const int ktn = (it + 1) * TK_;
        if (it + 1 < NTILE_) {
            #pragma unroll
            for (int m = 0; m < 8; m++) {
                int idx = m * GT_ + tid;
                int r = idx >> 6, c = idx & 63;
                cp_async16(xsa[nxt] + (unsigned)(r * 1024 + c * 16),
                           inT + (size_t)(ktn + r) * 256 + c * 4);
            }
            #pragma unroll
            for (int m = 0; m < 2; m++) {
                int idx = m * GT_ + tid;
                int r = idx >> 3, c = idx & 7;
                cp_async16(wsa[nxt] + (unsigned)(r * (WRS_ * 4) + c * 16),
                           wbase + (size_t)r * 512 + ktn + c * 4);
            }
            CP_COMMIT();
        }

        // compute on cur
        const float* xb = Xs[cur];
        const float* wr = Wr[cur] + (jq * 8) * WRS_;   // 8 rows (broadcast reads)
        #pragma unroll 4
        for (int k = 0; k < TK_; k++) {
            const float* xr = xb + k * 256;
            ull xv0 = *(const ull*)(xr + 2 * ip);
            ull xv1 = *(const ull*)(xr + 2 * ip + 64);
            ull xv2 = *(const ull*)(xr + 2 * ip + 128);
            ull xv3 = *(const ull*)(xr + 2 * ip + 192);
            ull wp0 = pk2(wr[0 * WRS_ + k], wr[0 * WRS_ + k]);
            ull wp1 = pk2(wr[1 * WRS_ + k], wr[1 * WRS_ + k]);
            ull wp2 = pk2(wr[2 * WRS_ + k], wr[2 * WRS_ + k]);
            ull wp3 = pk2(wr[3 * WRS_ + k], wr[3 * WRS_ + k]);
            ull wp4 = pk2(wr[4 * WRS_ + k], wr[4 * WRS_ + k]);
            ull wp5 = pk2(wr[5 * WRS_ + k], wr[5 * WRS_ + k]);
            ull wp6 = pk2(wr[6 * WRS_ + k], wr[6 * WRS_ + k]);
            ull wp7 = pk2(wr[7 * WRS_ + k], wr[7 * WRS_ + k]);
            fma2(acc[0][0], xv0, wp0); fma2(acc[0][1], xv1, wp0);
            fma2(acc[0][2], xv2, wp0); fma2(acc[0][3], xv3, wp0);
            fma2(acc[1][0], xv0, wp1); fma2(acc[1][1], xv1, wp1);
            fma2(acc[1][2], xv2, wp1); fma2(acc[1][3], xv3, wp1);
            fma2(acc[2][0], xv0, wp2); fma2(acc[2][1], xv1, wp2);
            fma2(acc[2][2], xv2, wp2); fma2(acc[2][3], xv3, wp2);
            fma2(acc[3][0], xv0, wp3); fma2(acc[3][1], xv1, wp3);
            fma2(acc[3][2], xv2, wp3); fma2(acc[3][3], xv3, wp3);
            fma2(acc[4][0], xv0, wp4); fma2(acc[4][1], xv1, wp4);
            fma2(acc[4][2], xv2, wp4); fma2(acc[4][3], xv3, wp4);
            fma2(acc[5][0], xv0, wp5); fma2(acc[5][1], xv1, wp5);
            fma2(acc[5][2], xv2, wp5); fma2(acc[5][3], xv3, wp5);
            fma2(acc[6][0], xv0, wp6); fma2(acc[6][1], xv1, wp6);
            fma2(acc[6][2], xv2, wp6); fma2(acc[6][3], xv3, wp6);
            fma2(acc[7][0], xv0, wp7); fma2(acc[7][1], xv1, wp7);
            fma2(acc[7][2], xv2, wp7); fma2(acc[7][3], xv3, wp7);
        }

        CP_WAIT0();
        __syncthreads();
    }

    // ---- epilogue: BN1 per j (warp-local stats), store ----
    #pragma unroll
    for (int jj = 0; jj < 8; jj++) {
        int j = j0 + jq * 8 + jj;
        float z[8];
        #pragma unroll
        for (int q = 0; q < 4; q++) {
            float a, b2;
            upk2(a, b2, acc[jj][q]);
            z[2 * q] = a; z[2 * q + 1] = b2;
        }
        float s1 = 0.f, s2 = 0.f;
        #pragma unroll
        for (int q = 0; q < 8; q++) { s1 += z[q]; s2 += z[q] * z[q]; }
        #pragma unroll
        for (int off = 16; off > 0; off >>= 1) {
            s1 += __shfl_xor_sync(0xffffffffu, s1, off);
            s2 += __shfl_xor_sync(0xffffffffu, s2, off);
        }
        float m   = s1 * (1.f / B_);
        float var = s2 * (1.f / B_) - m * m;
        float sc  = rsqrtf(var + EPS_) * gam[j];
        float sh  = bet[j] - m * sc;
        float* op = OUT + ((size_t)t * 512 + j) * 256;
        #pragma unroll
        for (int q = 0; q < 4; q++) {
            float ox = z[2 * q] * sc + sh;
            float oy = z[2 * q + 1] * sc + sh;
            *(ull*)(op + 2 * (ip + 32 * q)) = pk2(ox, oy);
        }
    }
    (void)bias;
}

// ---------------- sequential state scan: cp.async ring, warp-per-column -----
// h(t) = BN2_over_i( relu(Z[t] + h(t-1) * u) );  OUT[t] = h(t)
__global__ void __launch_bounds__(128) scan_kernel(
    const float* __restrict__ Z, const float* __restrict__ u,
    const float* __restrict__ g2, const float* __restrict__ be2,
    float* __restrict__ OUT) {

    __shared__ __align__(16) float ring[4][8][256];   // [warp][stage][i] 32KB

    const int tid  = threadIdx.x;
    const int w    = tid >> 5;
    const int lane = tid & 31;
    const int j    = blockIdx.x * 4 + w;
    const size_t base = (size_t)j * 256 + 8 * lane;
    const size_t tstr = (size_t)512 * 256;

    const float* zsrc = Z + base;
    float* hdst = OUT + base;
    float* myring = &ring[w][0][lane * 8];
    const unsigned rbase = (unsigned)__cvta_generic_to_shared(myring);

    const float uv = u[j], gv = g2[j], bv = be2[j];
    float h[8];
    #pragma unroll
    for (int q = 0; q < 8; q++) h[q] = 0.f;

    // preload stages 0..6 (one commit group per stage)
    #pragma unroll
    for (int s = 0; s < 7; s++) {
        cp_async16(rbase + (unsigned)(s * 1024),      zsrc + (size_t)s * tstr);
        cp_async16(rbase + (unsigned)(s * 1024) + 16, zsrc + (size_t)s * tstr + 4);
        CP_COMMIT();
    }

    for (int t = 0; t < T_; t++) {
        CP_WAIT6();    // stage t resident (own data; no cross-lane use)
        const float* zr = myring + (t & 7) * 256;
        float4 z0 = *(const float4*)(zr);
        float4 z1 = *(const float4*)(zr + 4);

        int tp = t + 7;
        if (tp < T_) {
            cp_async16(rbase + (unsigned)((tp & 7) * 1024),
                       zsrc + (size_t)tp * tstr);
            cp_async16(rbase + (unsigned)((tp & 7) * 1024) + 16,
                       zsrc + (size_t)tp * tstr + 4);
        }
        CP_COMMIT();

        float y[8];
        y[0] = fmaxf(fmaf(h[0], uv, z0.x), 0.f);
        y[1] = fmaxf(fmaf(h[1], uv, z0.y), 0.f);
        y[2] = fmaxf(fmaf(h[2], uv, z0.z), 0.f);
        y[3] = fmaxf(fmaf(h[3], uv, z0.w), 0.f);
        y[4] = fmaxf(fmaf(h[4], uv, z1.x), 0.f);
        y[5] = fmaxf(fmaf(h[5], uv, z1.y), 0.f);
        y[6] = fmaxf(fmaf(h[6], uv, z1.z), 0.f);
        y[7] = fmaxf(fmaf(h[7], uv, z1.w), 0.f);

        float s1 = 0.f, s2 = 0.f;
        #pragma unroll
        for (int q = 0; q < 8; q++) { s1 += y[q]; s2 += y[q] * y[q]; }
        #pragma unroll
        for (int off = 16; off > 0; off >>= 1) {
            s1 += __shfl_xor_sync(0xffffffffu, s1, off);
            s2 += __shfl_xor_sync(0xffffffffu, s2, off);
        }
        float m   = s1 * (1.f / B_);
        float var = s2 * (1.f / B_) - m * m;
        float sc  = rsqrtf(var + EPS_) * gv;
        float sh  = bv - m * sc;
        #pragma unroll
        for (int q = 0; q < 8; q++) h[q] = y[q] * sc + sh;

        float* op = hdst + (size_t)t * tstr;
        *(float4*)(op)     = make_float4(h[0], h[1], h[2], h[3]);
        *(float4*)(op + 4) = make_float4(h[4], h[5], h[6], h[7]);
    }
}

// ---------------- head: logits + log_softmax ----------------
__global__ void __launch_bounds__(256) head_kernel(
    const float* __restrict__ HM,
    const float* __restrict__ Wfc, const float* __restrict__ bfc,
    float* __restrict__ out) {

    __shared__ float hrow[H_];
    __shared__ float shd[8];

    const int r   = blockIdx.x;
    const int tid = threadIdx.x;

    hrow[tid]       = HM[(size_t)tid * 256 + r];
    hrow[tid + 256] = HM[(size_t)(tid + 256) * 256 + r];
    __syncthreads();

    float acc = bfc[tid];
    const float4* wrow = (const float4*)(Wfc + (size_t)tid * H_);
    #pragma unroll 4
    for (int j4 = 0; j4 < H_ / 4; j4++) {
        float4 w = wrow[j4];
        acc = fmaf(hrow[4 * j4 + 0], w.x, acc);
        acc = fmaf(hrow[4 * j4 + 1], w.y, acc);
        acc = fmaf(hrow[4 * j4 + 2], w.z, acc);
        acc = fmaf(hrow[4 * j4 + 3], w.w, acc);
    }

    float v = acc;
    #pragma unroll
    for (int off = 16; off > 0; off >>= 1)
        v = fmaxf(v, __shfl_xor_sync(0xffffffffu, v, off));
    if ((tid & 31) == 0) shd[tid >> 5] = v;
    __syncthreads();
    float mx = shd[0];
    #pragma unroll
    for (int w = 1; w < 8; w++) mx = fmaxf(mx, shd[w]);
    __syncthreads();

    float e = expf(acc - mx);
    float sv = e;
    #pragma unroll
    for (int off = 16; off > 0; off >>= 1)
        sv += __shfl_xor_sync(0xffffffffu, sv, off);
    if ((tid & 31) == 0) shd[tid >> 5] = sv;
    __syncthreads();
    float se = 0.f;
    #pragma unroll
    for (int w = 0; w < 8; w++) se += shd[w];

    out[(size_t)r * O_ + tid] = acc - mx - logf(se);
}

// ---------------- harness entry ----------------
extern "C" void kernel_launch(void* const* d_in, const int* in_sizes, int n_in,
                              void* d_out, int out_size) {
    (void)in_sizes; (void)n_in; (void)out_size;
    const float* x    = (const float*)d_in[0];
    const float* W0   = (const float*)d_in[1];
    const float* b0   = (const float*)d_in[2];
    const float* u0   = (const float*)d_in[3];
    const float* g10  = (const float*)d_in[4];
    const float* be10 = (const float*)d_in[5];
    const float* g20  = (const float*)d_in[6];
    const float* be20 = (const float*)d_in[7];
    const float* Wm   = (const float*)d_in[8];
    const float* bm   = (const float*)d_in[9];
    const float* um   = (const float*)d_in[10];
    const float* g1m  = (const float*)d_in[11];
    const float* be1m = (const float*)d_in[12];
    const float* g2m  = (const float*)d_in[13];
    const float* be2m = (const float*)d_in[14];
    const float* Wfc  = (const float*)d_in[15];
    const float* bfc  = (const float*)d_in[16];
    float* out = (float*)d_out;

    static int attr_set = 0;
    if (!attr_set) {
        cudaFuncSetAttribute(gemm_bn_kernel,
                             cudaFuncAttributeMaxDynamicSharedMemorySize, GEMM_SMEM);
        attr_set = 1;
    }

    float* bufA;  cudaGetSymbolAddress((void**)&bufA, d_bufA);
    float* bufB;  cudaGetSymbolAddress((void**)&bufB, d_bufB);
    float* xT;    cudaGetSymbolAddress((void**)&xT,   d_xT);

    transpose_kernel<<<dim3(T_, D_ / 32, B_ / 32), dim3(32, 32)>>>(x);
    gemm_bn_kernel<<<dim3(T_, H_ / TJ_), GT_, GEMM_SMEM>>>(xT, W0, b0, g10, be10, bufA);
    scan_kernel<<<128, 128>>>(bufA, u0, g20, be20, bufB);
    gemm_bn_kernel<<<dim3(T_, H_ / TJ_), GT_, GEMM_SMEM>>>(bufB, Wm, bm, g1m, be1m, bufA);
    scan_kernel<<<128, 128>>>(bufA, um, g2m, be2m, bufB);
    gemm_bn_kernel<<<dim3(T_, H_ / TJ_), GT_, GEMM_SMEM>>>(bufB, Wm, bm, g1m, be1m, bufA);
    scan_kernel<<<128, 128>>>(bufA, um, g2m, be2m, bufB);
    head_kernel<<<O_, 256>>>(bufB + (size_t)(T_ - 1) * H_ * B_, Wfc, bfc, out);
}